// round 1
// baseline (speedup 1.0000x reference)
#include <cuda_runtime.h>

#define MULC 64
#define BASE 9
#define ROW  576     // MULC*BASE
#define ROW4 144     // ROW/4
#define NP   11
#define EB   4       // edges per tile
#define TPB  256

// ---------------------------------------------------------------------------
// Sparse structure of the dense w3j buffer (p, k_out, i_in1, j_in2), derived
// from real-spherical-harmonic selection rules. 83 nonzero entries collapse to
// 39 distinct values (permutation symmetry of the 3j symbol, even l-sums).
// Values are LOADED from the input w3j buffer at a representative index, so
// numerics match the reference bit-for-bit at the coefficient level.
// ---------------------------------------------------------------------------

// X(v, p, k, i, j): representative buffer index for value v of path p
#define VAL_LIST(X) \
  X( 0, 0,0,0,0) \
  X( 1, 1,1,0,1) \
  X( 2, 2,4,0,4) \
  X( 3, 3,1,1,0) \
  X( 4, 4,0,1,1) \
  X( 5, 5,4,3,1) \
  X( 6, 5,5,1,2) \
  X( 7, 5,6,1,1) \
  X( 8, 5,6,2,2) \
  X( 9, 5,6,3,3) \
  X(10, 5,7,2,3) \
  X(11, 5,8,1,1) \
  X(12, 5,8,3,3) \
  X(13, 6,1,3,4) \
  X(14, 6,2,1,5) \
  X(15, 6,1,1,6) \
  X(16, 6,2,2,6) \
  X(17, 6,3,3,6) \
  X(18, 6,3,2,7) \
  X(19, 6,1,1,8) \
  X(20, 6,3,3,8) \
  X(21, 7,4,4,0) \
  X(22, 8,1,4,3) \
  X(23, 8,2,5,1) \
  X(24, 8,1,6,1) \
  X(25, 8,2,6,2) \
  X(26, 8,3,6,3) \
  X(27, 8,3,7,2) \
  X(28, 8,1,8,1) \
  X(29, 8,3,8,3) \
  X(30, 9,0,4,4) \
  X(31,10,6,6,6) \
  X(32,10,6,7,7) \
  X(33,10,6,5,5) \
  X(34,10,6,8,8) \
  X(35,10,6,4,4) \
  X(36,10,8,7,7) \
  X(37,10,8,5,5) \
  X(38,10,4,7,5)

#define NV 39

// X(v, k, i, j): the 83 FMA terms, each referencing a value id
#define TERM_LIST(X) \
  X( 0, 0,0,0) \
  X( 1, 1,0,1) X( 1, 2,0,2) X( 1, 3,0,3) \
  X( 2, 4,0,4) X( 2, 5,0,5) X( 2, 6,0,6) X( 2, 7,0,7) X( 2, 8,0,8) \
  X( 3, 1,1,0) X( 3, 2,2,0) X( 3, 3,3,0) \
  X( 4, 0,1,1) X( 4, 0,2,2) X( 4, 0,3,3) \
  X( 5, 4,3,1) X( 5, 4,1,3) \
  X( 6, 5,1,2) X( 6, 5,2,1) \
  X( 7, 6,1,1) X( 8, 6,2,2) X( 9, 6,3,3) \
  X(10, 7,2,3) X(10, 7,3,2) \
  X(11, 8,1,1) X(12, 8,3,3) \
  X(13, 1,3,4) X(13, 3,1,4) \
  X(14, 2,1,5) X(14, 1,2,5) \
  X(15, 1,1,6) X(16, 2,2,6) X(17, 3,3,6) \
  X(18, 3,2,7) X(18, 2,3,7) \
  X(19, 1,1,8) X(20, 3,3,8) \
  X(21, 4,4,0) X(21, 5,5,0) X(21, 6,6,0) X(21, 7,7,0) X(21, 8,8,0) \
  X(22, 1,4,3) X(22, 3,4,1) \
  X(23, 2,5,1) X(23, 1,5,2) \
  X(24, 1,6,1) X(25, 2,6,2) X(26, 3,6,3) \
  X(27, 3,7,2) X(27, 2,7,3) \
  X(28, 1,8,1) X(29, 3,8,3) \
  X(30, 0,4,4) X(30, 0,5,5) X(30, 0,6,6) X(30, 0,7,7) X(30, 0,8,8) \
  X(31, 6,6,6) \
  X(32, 6,7,7) X(32, 7,7,6) X(32, 7,6,7) \
  X(33, 6,5,5) X(33, 5,5,6) X(33, 5,6,5) \
  X(34, 6,8,8) X(34, 8,8,6) X(34, 8,6,8) \
  X(35, 6,4,4) X(35, 4,4,6) X(35, 4,6,4) \
  X(36, 8,7,7) X(36, 7,8,7) X(36, 7,7,8) \
  X(37, 8,5,5) X(37, 5,8,5) X(37, 5,5,8) \
  X(38, 4,7,5) X(38, 4,5,7) X(38, 7,4,5) X(38, 5,4,7) X(38, 7,5,4) X(38, 5,7,4)

__global__ void __launch_bounds__(TPB, 2)
tp_kernel(const float* __restrict__ x1, const float* __restrict__ x2,
          const float* __restrict__ wts, const float* __restrict__ w3j,
          float* __restrict__ out, int nz)
{
    __shared__ float s1[EB * ROW];
    __shared__ float s2[EB * ROW];
    __shared__ float so[EB * ROW];

    const int tid = threadIdx.x;
    const int u   = tid & 63;   // channel
    const int e   = tid >> 6;   // edge within tile

    // Fold per-channel path weights into the 39 distinct CG values (registers,
    // persistent across the whole grid-stride loop).
    float cw[NV];
    {
        float wv[NP];
        #pragma unroll
        for (int p = 0; p < NP; ++p) wv[p] = wts[u * NP + p];
#define LOADV(v, p, k, i, j) cw[v] = wv[p] * w3j[(p)*729 + (k)*81 + (i)*9 + (j)];
        VAL_LIST(LOADV)
#undef LOADV
    }

    const int ntiles = (nz + EB - 1) / EB;
    for (int tile = blockIdx.x; tile < ntiles; tile += gridDim.x) {
        const int z0     = tile * EB;
        const int nerows = (z0 + EB <= nz) ? EB : (nz - z0);
        const int nvec   = nerows * ROW4;

        // Stage x1/x2 rows into smem with fully-coalesced float4 loads.
        const float4* g1 = (const float4*)x1 + (size_t)z0 * ROW4;
        const float4* g2 = (const float4*)x2 + (size_t)z0 * ROW4;
        float4* s1v = (float4*)s1;
        float4* s2v = (float4*)s2;
        for (int idx = tid; idx < nvec; idx += TPB) {
            s1v[idx] = g1[idx];
            s2v[idx] = g2[idx];
        }
        __syncthreads();

        if (e < nerows) {
            // stride-9 smem reads: 9 is odd -> conflict-free across 32 banks
            const float* p1 = s1 + e * ROW + u * BASE;
            const float* p2 = s2 + e * ROW + u * BASE;
            float a[BASE], b[BASE], acc[BASE];
            #pragma unroll
            for (int q = 0; q < BASE; ++q) {
                a[q] = p1[q];
                b[q] = p2[q];
                acc[q] = 0.0f;
            }
#define DOFMA(v, k, i, j) acc[k] = fmaf(cw[v], a[i] * b[j], acc[k]);
            TERM_LIST(DOFMA)
#undef DOFMA
            float* po = so + e * ROW + u * BASE;
            #pragma unroll
            for (int q = 0; q < BASE; ++q) po[q] = acc[q];
        }
        __syncthreads();

        // Coalesced float4 store of the tile's output.
        float4* go = (float4*)out + (size_t)z0 * ROW4;
        const float4* sov = (const float4*)so;
        for (int idx = tid; idx < nvec; idx += TPB) go[idx] = sov[idx];
        __syncthreads();   // protect s1/s2/so before next tile overwrites them
    }
}

extern "C" void kernel_launch(void* const* d_in, const int* in_sizes, int n_in,
                              void* d_out, int out_size)
{
    const float* x1  = (const float*)d_in[0];
    const float* x2  = (const float*)d_in[1];
    const float* wts = (const float*)d_in[2];
    const float* w3j = (const float*)d_in[3];
    float* out = (float*)d_out;

    const int nz = in_sizes[0] / ROW;   // 50000
    // ~2 blocks/SM (148 SMs), persistent grid-stride over tiles so the folded
    // coefficient setup is paid once per block, not per tile.
    tp_kernel<<<296, TPB>>>(x1, x2, wts, w3j, out, nz);
}

// round 2
// speedup vs baseline: 1.5326x; 1.5326x over previous
#include <cuda_runtime.h>
#include <cstdint>

#define MULC 64
#define BASE 9
#define ROW  576     // MULC*BASE
#define ROW4 144     // ROW/4
#define NP   11
#define EB   8       // edges per tile (50000 % 8 == 0)
#define TPB  256
#define NV   39

// ---------------------------------------------------------------------------
// Sparse structure of the dense w3j buffer (p, k_out, i_in1, j_in2). 83
// nonzeros collapsing to 39 distinct values; values are loaded from the input
// w3j buffer so numerics match the reference exactly.
// ---------------------------------------------------------------------------

// X(v, p, k, i, j): representative buffer index for value v of path p
#define VAL_LIST(X) \
  X( 0, 0,0,0,0) \
  X( 1, 1,1,0,1) \
  X( 2, 2,4,0,4) \
  X( 3, 3,1,1,0) \
  X( 4, 4,0,1,1) \
  X( 5, 5,4,3,1) \
  X( 6, 5,5,1,2) \
  X( 7, 5,6,1,1) \
  X( 8, 5,6,2,2) \
  X( 9, 5,6,3,3) \
  X(10, 5,7,2,3) \
  X(11, 5,8,1,1) \
  X(12, 5,8,3,3) \
  X(13, 6,1,3,4) \
  X(14, 6,2,1,5) \
  X(15, 6,1,1,6) \
  X(16, 6,2,2,6) \
  X(17, 6,3,3,6) \
  X(18, 6,3,2,7) \
  X(19, 6,1,1,8) \
  X(20, 6,3,3,8) \
  X(21, 7,4,4,0) \
  X(22, 8,1,4,3) \
  X(23, 8,2,5,1) \
  X(24, 8,1,6,1) \
  X(25, 8,2,6,2) \
  X(26, 8,3,6,3) \
  X(27, 8,3,7,2) \
  X(28, 8,1,8,1) \
  X(29, 8,3,8,3) \
  X(30, 9,0,4,4) \
  X(31,10,6,6,6) \
  X(32,10,6,7,7) \
  X(33,10,6,5,5) \
  X(34,10,6,8,8) \
  X(35,10,6,4,4) \
  X(36,10,8,7,7) \
  X(37,10,8,5,5) \
  X(38,10,4,7,5)

// X(v, k, i, j): the 83 FMA terms, each referencing a value id
#define TERM_LIST(X) \
  X( 0, 0,0,0) \
  X( 1, 1,0,1) X( 1, 2,0,2) X( 1, 3,0,3) \
  X( 2, 4,0,4) X( 2, 5,0,5) X( 2, 6,0,6) X( 2, 7,0,7) X( 2, 8,0,8) \
  X( 3, 1,1,0) X( 3, 2,2,0) X( 3, 3,3,0) \
  X( 4, 0,1,1) X( 4, 0,2,2) X( 4, 0,3,3) \
  X( 5, 4,3,1) X( 5, 4,1,3) \
  X( 6, 5,1,2) X( 6, 5,2,1) \
  X( 7, 6,1,1) X( 8, 6,2,2) X( 9, 6,3,3) \
  X(10, 7,2,3) X(10, 7,3,2) \
  X(11, 8,1,1) X(12, 8,3,3) \
  X(13, 1,3,4) X(13, 3,1,4) \
  X(14, 2,1,5) X(14, 1,2,5) \
  X(15, 1,1,6) X(16, 2,2,6) X(17, 3,3,6) \
  X(18, 3,2,7) X(18, 2,3,7) \
  X(19, 1,1,8) X(20, 3,3,8) \
  X(21, 4,4,0) X(21, 5,5,0) X(21, 6,6,0) X(21, 7,7,0) X(21, 8,8,0) \
  X(22, 1,4,3) X(22, 3,4,1) \
  X(23, 2,5,1) X(23, 1,5,2) \
  X(24, 1,6,1) X(25, 2,6,2) X(26, 3,6,3) \
  X(27, 3,7,2) X(27, 2,7,3) \
  X(28, 1,8,1) X(29, 3,8,3) \
  X(30, 0,4,4) X(30, 0,5,5) X(30, 0,6,6) X(30, 0,7,7) X(30, 0,8,8) \
  X(31, 6,6,6) \
  X(32, 6,7,7) X(32, 7,7,6) X(32, 7,6,7) \
  X(33, 6,5,5) X(33, 5,5,6) X(33, 5,6,5) \
  X(34, 6,8,8) X(34, 8,8,6) X(34, 8,6,8) \
  X(35, 6,4,4) X(35, 4,4,6) X(35, 4,6,4) \
  X(36, 8,7,7) X(36, 7,8,7) X(36, 7,7,8) \
  X(37, 8,5,5) X(37, 5,8,5) X(37, 5,5,8) \
  X(38, 4,7,5) X(38, 4,5,7) X(38, 7,4,5) X(38, 5,4,7) X(38, 7,5,4) X(38, 5,7,4)

#define TILE_FLOATS (EB * ROW)                 // 4608
#define SMEM_FLOATS (5 * TILE_FLOATS)          // 2x s1, 2x s2, 1x so
#define SMEM_BYTES  (SMEM_FLOATS * 4)          // 92160

__device__ __forceinline__ void cp_async16(uint32_t saddr, const void* gptr) {
    asm volatile("cp.async.cg.shared.global [%0], [%1], 16;" :: "r"(saddr), "l"(gptr));
}
__device__ __forceinline__ void cp_commit() {
    asm volatile("cp.async.commit_group;");
}
__device__ __forceinline__ void cp_wait1() {
    asm volatile("cp.async.wait_group 1;");
}

__global__ void __launch_bounds__(TPB, 2)
tp_kernel(const float* __restrict__ x1, const float* __restrict__ x2,
          const float* __restrict__ wts, const float* __restrict__ w3j,
          float* __restrict__ out, int nz)
{
    extern __shared__ float smem[];
    float* s1 = smem;                    // [2][TILE_FLOATS]
    float* s2 = smem + 2 * TILE_FLOATS;  // [2][TILE_FLOATS]
    float* so = smem + 4 * TILE_FLOATS;  // [TILE_FLOATS]

    const int tid = threadIdx.x;
    const int u   = tid & 63;

    // Fold per-channel path weights into the 39 distinct CG values.
    float cw[NV];
    {
        float wv[NP];
        #pragma unroll
        for (int p = 0; p < NP; ++p) wv[p] = wts[u * NP + p];
#define LOADV(v, p, k, i, j) cw[v] = wv[p] * w3j[(p)*729 + (k)*81 + (i)*9 + (j)];
        VAL_LIST(LOADV)
#undef LOADV
    }

    const int ntiles = (nz + EB - 1) / EB;
    const int G = gridDim.x;

    const uint32_t s1b = (uint32_t)__cvta_generic_to_shared(s1);
    const uint32_t s2b = (uint32_t)__cvta_generic_to_shared(s2);

    // ---- prologue: prefetch first tile for this block ----
    int tile = blockIdx.x;
    if (tile < ntiles) {
        const int z0   = tile * EB;
        const int nv4  = min(EB, nz - z0) * ROW4;
        const float4* g1 = (const float4*)x1 + (size_t)z0 * ROW4;
        const float4* g2 = (const float4*)x2 + (size_t)z0 * ROW4;
        for (int idx = tid; idx < nv4; idx += TPB) {
            cp_async16(s1b + (uint32_t)idx * 16u, g1 + idx);
            cp_async16(s2b + (uint32_t)idx * 16u, g2 + idx);
        }
    }
    cp_commit();

    int buf = 0;
    for (; tile < ntiles; tile += G) {
        // ---- prefetch next tile into the other buffer ----
        const int nxt = tile + G;
        if (nxt < ntiles) {
            const int z0n  = nxt * EB;
            const int nv4n = min(EB, nz - z0n) * ROW4;
            const uint32_t d1 = s1b + (uint32_t)(buf ^ 1) * (TILE_FLOATS * 4u);
            const uint32_t d2 = s2b + (uint32_t)(buf ^ 1) * (TILE_FLOATS * 4u);
            const float4* g1 = (const float4*)x1 + (size_t)z0n * ROW4;
            const float4* g2 = (const float4*)x2 + (size_t)z0n * ROW4;
            for (int idx = tid; idx < nv4n; idx += TPB) {
                cp_async16(d1 + (uint32_t)idx * 16u, g1 + idx);
                cp_async16(d2 + (uint32_t)idx * 16u, g2 + idx);
            }
        }
        cp_commit();
        cp_wait1();          // current tile's data has landed
        __syncthreads();     // visible to all; also fences so reuse from prev iter

        const int z0     = tile * EB;
        const int nerows = min(EB, nz - z0);

        // ---- compute: 2 items (edge,channel) per thread ----
        const float* cs1 = s1 + buf * TILE_FLOATS;
        const float* cs2 = s2 + buf * TILE_FLOATS;
        #pragma unroll
        for (int it = 0; it < 2; ++it) {
            const int e = (tid >> 6) + it * (TPB >> 6);   // 0..7
            if (e < nerows) {
                const float* p1 = cs1 + e * ROW + u * BASE;
                const float* p2 = cs2 + e * ROW + u * BASE;
                float a[BASE], b[BASE], acc[BASE];
                #pragma unroll
                for (int q = 0; q < BASE; ++q) {
                    a[q] = p1[q];
                    b[q] = p2[q];
                    acc[q] = 0.0f;
                }
#define DOFMA(v, k, i, j) acc[k] = fmaf(cw[v], a[i] * b[j], acc[k]);
                TERM_LIST(DOFMA)
#undef DOFMA
                float* po = so + e * ROW + u * BASE;
                #pragma unroll
                for (int q = 0; q < BASE; ++q) po[q] = acc[q];
            }
        }
        __syncthreads();

        // ---- coalesced float4 store of the tile's output ----
        const int nv4 = nerows * ROW4;
        float4* go = (float4*)out + (size_t)z0 * ROW4;
        const float4* sov = (const float4*)so;
        for (int idx = tid; idx < nv4; idx += TPB) go[idx] = sov[idx];

        buf ^= 1;
        // so-reuse is protected by next iteration's wait+__syncthreads()
    }
}

extern "C" void kernel_launch(void* const* d_in, const int* in_sizes, int n_in,
                              void* d_out, int out_size)
{
    const float* x1  = (const float*)d_in[0];
    const float* x2  = (const float*)d_in[1];
    const float* wts = (const float*)d_in[2];
    const float* w3j = (const float*)d_in[3];
    float* out = (float*)d_out;

    const int nz = in_sizes[0] / ROW;   // 50000

    // Attribute set is not a stream operation: capture-safe, no allocation.
    cudaFuncSetAttribute(tp_kernel, cudaFuncAttributeMaxDynamicSharedMemorySize,
                         SMEM_BYTES);
    tp_kernel<<<296, TPB, SMEM_BYTES>>>(x1, x2, wts, w3j, out, nz);
}